// round 2
// baseline (speedup 1.0000x reference)
#include <cuda_runtime.h>
#include <cstddef>

#define B_ 1024
#define E_ 8192
#define R_ 16
#define D_ 128
#define BT 64
#define ET 64
#define EBLK (E_/ET)   // 128

// Scratch (no allocation allowed)
__device__ float g_c[R_*E_];       // c[r,e] = zz[e] - 2*rz[r,e]
__device__ float g_g[E_];          // g[e]   = zz[e] + 2*zq[e]
__device__ float g_u[B_*R_];       // u[b,r] = hh[b] + rr[r] + 2*hr[b,r]
__device__ float g_v[B_];          // v[b]   = tt[b] + qq - 2*qt[b]
__device__ float g_part[B_*EBLK];  // partials, [b][eblk]

__device__ __forceinline__ float wsum(float v){
  v += __shfl_xor_sync(0xffffffffu, v, 16);
  v += __shfl_xor_sync(0xffffffffu, v, 8);
  v += __shfl_xor_sync(0xffffffffu, v, 4);
  v += __shfl_xor_sync(0xffffffffu, v, 2);
  v += __shfl_xor_sync(0xffffffffu, v, 1);
  return v;
}
__device__ __forceinline__ float dot4(float4 a, float4 b){
  return fmaf(a.x,b.x, fmaf(a.y,b.y, fmaf(a.z,b.z, a.w*b.w)));
}
__device__ __forceinline__ float sqrt_approx(float x){
  float y; asm("sqrt.approx.f32 %0, %1;" : "=f"(y) : "f"(x)); return y;
}
// ---- packed f32x2 helpers (FFMA2 path) ----
typedef unsigned long long ull;
__device__ __forceinline__ ull pk2(float lo, float hi){
  ull r; asm("mov.b64 %0, {%1,%2};" : "=l"(r) : "f"(lo), "f"(hi)); return r;
}
__device__ __forceinline__ float2 upk2(ull v){
  float2 f; asm("mov.b64 {%0,%1}, %2;" : "=f"(f.x), "=f"(f.y) : "l"(v)); return f;
}
__device__ __forceinline__ void fma2(ull& d, ull a, ull b){
  asm("fma.rn.f32x2 %0, %1, %2, %0;" : "+l"(d) : "l"(a), "l"(b));
}

// ---------------- per-entity precompute: zz, g, c ----------------
__global__ void k_pre_e(const float* __restrict__ Etab,
                        const float* __restrict__ rules,
                        const int* __restrict__ qrelp){
  __shared__ __align__(16) float rs[R_*D_];
  int tid = threadIdx.x;
  for (int i = tid; i < R_*D_; i += blockDim.x) rs[i] = rules[i];
  __syncthreads();
  int qrel = *qrelp;
  int lane = tid & 31, warp = tid >> 5;
  int e = blockIdx.x*8 + warp;
  float4 zv = ((const float4*)(Etab + (size_t)e*D_))[lane];
  float zz = wsum(dot4(zv, zv));
  float4 qv = ((const float4*)(rs + qrel*D_))[lane];
  float zq = wsum(dot4(zv, qv));
  if (lane == 0) g_g[e] = zz + 2.f*zq;
  #pragma unroll
  for (int r = 0; r < R_; r++){
    float4 rv = ((const float4*)(rs + r*D_))[lane];
    float rz = wsum(dot4(zv, rv));
    if (lane == 0) g_c[r*E_ + e] = zz - 2.f*rz;
  }
}

// ---------------- per-batch precompute: u, v ----------------
__global__ void k_pre_b(const float* __restrict__ Etab,
                        const float* __restrict__ rules,
                        const int* __restrict__ head,
                        const int* __restrict__ tail,
                        const int* __restrict__ qrelp){
  __shared__ __align__(16) float rs[R_*D_];
  __shared__ float rr[R_];
  int tid = threadIdx.x;
  for (int i = tid; i < R_*D_; i += blockDim.x) rs[i] = rules[i];
  __syncthreads();
  if (tid < R_){
    float s = 0.f;
    for (int k = 0; k < D_; k++) s = fmaf(rs[tid*D_+k], rs[tid*D_+k], s);
    rr[tid] = s;
  }
  __syncthreads();
  int qrel = *qrelp;
  int lane = tid & 31, warp = tid >> 5;
  int b = blockIdx.x*8 + warp;
  float4 hv = ((const float4*)(Etab + (size_t)head[b]*D_))[lane];
  float4 tv = ((const float4*)(Etab + (size_t)tail[b]*D_))[lane];
  float hh = wsum(dot4(hv, hv));
  float tt = wsum(dot4(tv, tv));
  float4 qv = ((const float4*)(rs + qrel*D_))[lane];
  float tq = wsum(dot4(tv, qv));
  if (lane == 0) g_v[b] = tt + rr[qrel] - 2.f*tq;
  #pragma unroll
  for (int r = 0; r < R_; r++){
    float4 rv = ((const float4*)(rs + r*D_))[lane];
    float hr = wsum(dot4(hv, rv));
    if (lane == 0) g_u[b*R_ + r] = hh + rr[r] + 2.f*hr;
  }
}

// ---------------- main fused kernel ----------------
// smem floats: hs 8192 (k-major), ts 8192 (k-major), zs 8192 (k-major),
//              cs 1024, us 1024, gs 64, vs 64, hix/tix 128 ints
#define SMEM_FLOATS (8192*3 + 1024*2 + 64*2 + 128)

__global__ __launch_bounds__(256, 1) void k_main(const float* __restrict__ Etab,
                                                 const int* __restrict__ head,
                                                 const int* __restrict__ tail){
  extern __shared__ __align__(16) float sm[];
  float* hs = sm;               // [128][64] k-major: hs[k*64 + b]
  float* ts = hs + 8192;        // [128][64]
  float* zs = ts + 8192;        // [128][64]
  float* cs = zs + 8192;        // [16][64]
  float* us = cs + 1024;        // [64][16]
  float* gs = us + 1024;        // [64]
  float* vs = gs + 64;          // [64]
  int*  hix = (int*)(vs + 64);  // [64]
  int*  tix = hix + 64;         // [64]

  int tid = threadIdx.x;
  int e0 = blockIdx.x * ET, b0 = blockIdx.y * BT;

  if (tid < 64){ hix[tid] = head[b0+tid]; tix[tid] = tail[b0+tid]; vs[tid] = g_v[b0+tid]; }
  else if (tid < 128){ gs[tid-64] = g_g[e0 + tid - 64]; }
  for (int i = tid; i < BT*R_; i += 256) us[i] = g_u[b0*R_ + i];
  for (int i = tid; i < R_*ET; i += 256){
    int r = i >> 6, e = i & 63;
    cs[i] = g_c[r*E_ + e0 + e];
  }
  __syncthreads();

  // Load tiles into k-major smem. lane-per-row mapping: conflict-free STS.
  #pragma unroll
  for (int it = 0; it < 8; it++){
    int idx = it*256 + tid;
    int row = idx & 63, zc = idx >> 6;   // row within tile, float4 column
    float4 a = __ldg((const float4*)(Etab + (size_t)hix[row]*D_) + zc);
    hs[(zc*4+0)*64 + row] = a.x;
    hs[(zc*4+1)*64 + row] = a.y;
    hs[(zc*4+2)*64 + row] = a.z;
    hs[(zc*4+3)*64 + row] = a.w;
    float4 b = __ldg((const float4*)(Etab + (size_t)tix[row]*D_) + zc);
    ts[(zc*4+0)*64 + row] = b.x;
    ts[(zc*4+1)*64 + row] = b.y;
    ts[(zc*4+2)*64 + row] = b.z;
    ts[(zc*4+3)*64 + row] = b.w;
    float4 z = __ldg((const float4*)(Etab + (size_t)(e0+row)*D_) + zc);
    zs[(zc*4+0)*64 + row] = z.x;
    zs[(zc*4+1)*64 + row] = z.y;
    zs[(zc*4+2)*64 + row] = z.z;
    zs[(zc*4+3)*64 + row] = z.w;
  }
  __syncthreads();

  int tx = tid & 15, ty = tid >> 4;     // tx: e group (4 e's), ty: b group (4 b's)

  // packed accumulators: [ipair][j], ipair0=(b0,b1), ipair1=(b2,b3)
  ull hz2[2][4], zt2[2][4];
  ull z0 = pk2(0.f, 0.f);
  #pragma unroll
  for (int p = 0; p < 2; p++)
    #pragma unroll
    for (int j = 0; j < 4; j++){ hz2[p][j] = z0; zt2[p][j] = z0; }

  const float* hp = hs + ty*4;
  const float* tp = ts + ty*4;
  const float* zp = zs + tx*4;

  #pragma unroll 2
  for (int k = 0; k < 128; k++){
    float4 hv = *(const float4*)(hp + k*64);   // 4 b's at this k (broadcast LDS)
    float4 tv = *(const float4*)(tp + k*64);
    float4 zv = *(const float4*)(zp + k*64);   // 4 e's at this k
    ull h01 = pk2(hv.x, hv.y), h23 = pk2(hv.z, hv.w);
    ull t01 = pk2(tv.x, tv.y), t23 = pk2(tv.z, tv.w);
    float zj[4] = {zv.x, zv.y, zv.z, zv.w};
    #pragma unroll
    for (int j = 0; j < 4; j++){
      ull zd = pk2(zj[j], zj[j]);
      fma2(hz2[0][j], h01, zd);
      fma2(hz2[1][j], h23, zd);
      fma2(zt2[0][j], t01, zd);
      fma2(zt2[1][j], t23, zd);
    }
  }

  // unpack
  float hz[4][4], zt[4][4];
  #pragma unroll
  for (int j = 0; j < 4; j++){
    float2 a = upk2(hz2[0][j]); hz[0][j] = a.x; hz[1][j] = a.y;
    float2 b = upk2(hz2[1][j]); hz[2][j] = b.x; hz[3][j] = b.y;
    float2 c = upk2(zt2[0][j]); zt[0][j] = c.x; zt[1][j] = c.y;
    float2 d = upk2(zt2[1][j]); zt[2][j] = d.x; zt[3][j] = d.y;
  }

  // epilogue: s2 then sum_r sqrt(sq1)
  float s2v[4][4];
  #pragma unroll
  for (int i = 0; i < 4; i++){
    float vb = vs[ty*4+i];
    #pragma unroll
    for (int j = 0; j < 4; j++){
      float sq2 = fmaf(-2.f, zt[i][j], vb + gs[tx*4+j]);
      s2v[i][j] = sqrt_approx(fmaxf(sq2, 0.f));
    }
  }
  float S1[4][4];
  #pragma unroll
  for (int i = 0; i < 4; i++)
    #pragma unroll
    for (int j = 0; j < 4; j++) S1[i][j] = 0.f;

  #pragma unroll
  for (int r = 0; r < R_; r++){
    float ur[4], cr[4];
    #pragma unroll
    for (int i = 0; i < 4; i++) ur[i] = us[(ty*4+i)*R_ + r];
    #pragma unroll
    for (int j = 0; j < 4; j++) cr[j] = cs[r*64 + tx*4 + j];
    #pragma unroll
    for (int i = 0; i < 4; i++)
      #pragma unroll
      for (int j = 0; j < 4; j++){
        float x = fmaf(-2.f, hz[i][j], ur[i] + cr[j]);
        S1[i][j] += sqrt_approx(fmaxf(x, 0.f));
      }
  }

  float res[4];
  #pragma unroll
  for (int i = 0; i < 4; i++){
    float s = 0.f;
    #pragma unroll
    for (int j = 0; j < 4; j++) s = fmaf(S1[i][j], s2v[i][j], s);
    res[i] = s;
  }

  __syncthreads();
  #pragma unroll
  for (int i = 0; i < 4; i++) hs[(ty*4+i)*16 + tx] = res[i];
  __syncthreads();
  if (tid < 64){
    float s = 0.f;
    #pragma unroll
    for (int x = 0; x < 16; x++) s += hs[tid*16 + x];
    g_part[(size_t)(b0 + tid)*EBLK + blockIdx.x] = s;   // [b][eblk] layout
  }
}

// ---------------- final deterministic reduction (warp per b) ----------------
__global__ void k_final(float* __restrict__ out){
  int warp = threadIdx.x >> 5, lane = threadIdx.x & 31;
  int b = blockIdx.x*8 + warp;
  const float* p = g_part + (size_t)b*EBLK;
  float s = p[lane] + p[lane+32] + p[lane+64] + p[lane+96];
  s = wsum(s);
  if (lane == 0) out[b] = s * (1.f/(float)E_);
}

extern "C" void kernel_launch(void* const* d_in, const int* in_sizes, int n_in,
                              void* d_out, int out_size){
  const int*   head  = (const int*)d_in[0];
  const int*   tail  = (const int*)d_in[1];
  const int*   qrel  = (const int*)d_in[2];
  // d_in[3] = depth (fixed at 1, unused)
  const float* Etab  = (const float*)d_in[4];
  const float* rules = (const float*)d_in[5];
  float* out = (float*)d_out;

  size_t smem = (size_t)SMEM_FLOATS * sizeof(float);
  cudaFuncSetAttribute(k_main, cudaFuncAttributeMaxDynamicSharedMemorySize, (int)smem);

  k_pre_e<<<E_/8, 256>>>(Etab, rules, qrel);
  k_pre_b<<<B_/8, 256>>>(Etab, rules, head, tail, qrel);
  dim3 grid(E_/ET, B_/BT);
  k_main<<<grid, 256, smem>>>(Etab, head, tail);
  k_final<<<B_/8, 256>>>(out);
}

// round 7
// speedup vs baseline: 4.1814x; 4.1814x over previous
#include <cuda_runtime.h>
#include <cuda_bf16.h>
#include <cstdint>
#include <cstddef>

#define B_ 1024
#define E_ 8192
#define R_ 16
#define D_ 128
#define BT 64            // b per tile (A rows: 64 h + 64 t = 128)
#define ET2 128          // e per tile (N)
#define NTILE_E (E_/ET2) // 64

// ---- global scratch (no allocation allowed) ----
__device__ float g_c[R_*E_];       // c[r,e] = zz[e] - 2*rz[r,e]
__device__ float g_g[E_];          // g[e]   = zz[e] + 2*zq[e]
__device__ float g_u[B_*R_];       // u[b,r] = hh[b] + rr[r] + 2*hr[b,r]
__device__ float g_v[B_];          // v[b]   = tt[b] + qq - 2*qt[b]
__device__ float g_part[B_*NTILE_E];
__device__ __nv_bfloat16 g_Ebf[E_*D_];

__device__ __forceinline__ float wsum(float v){
  v += __shfl_xor_sync(0xffffffffu, v, 16);
  v += __shfl_xor_sync(0xffffffffu, v, 8);
  v += __shfl_xor_sync(0xffffffffu, v, 4);
  v += __shfl_xor_sync(0xffffffffu, v, 2);
  v += __shfl_xor_sync(0xffffffffu, v, 1);
  return v;
}
__device__ __forceinline__ float dot4(float4 a, float4 b){
  return fmaf(a.x,b.x, fmaf(a.y,b.y, fmaf(a.z,b.z, a.w*b.w)));
}
__device__ __forceinline__ float sqrt_approx(float x){
  float y; asm("sqrt.approx.f32 %0, %1;" : "=f"(y) : "f"(x)); return y;
}
__device__ __forceinline__ uint32_t smem_u32(const void* p){
  uint32_t a;
  asm("{ .reg .u64 t; cvta.to.shared.u64 t, %1; cvt.u32.u64 %0, t; }" : "=r"(a) : "l"(p));
  return a;
}
__device__ __forceinline__ void ldm4(uint32_t& r0, uint32_t& r1, uint32_t& r2, uint32_t& r3,
                                     uint32_t addr){
  asm volatile("ldmatrix.sync.aligned.m8n8.x4.shared.b16 {%0,%1,%2,%3}, [%4];"
    : "=r"(r0), "=r"(r1), "=r"(r2), "=r"(r3) : "r"(addr));
}
__device__ __forceinline__ void mma16816(float* d, const uint32_t* a, uint32_t b0, uint32_t b1){
  asm volatile("mma.sync.aligned.m16n8k16.row.col.f32.bf16.bf16.f32 "
    "{%0,%1,%2,%3}, {%4,%5,%6,%7}, {%8,%9}, {%0,%1,%2,%3};"
    : "+f"(d[0]), "+f"(d[1]), "+f"(d[2]), "+f"(d[3])
    : "r"(a[0]), "r"(a[1]), "r"(a[2]), "r"(a[3]), "r"(b0), "r"(b1));
}

// ---------------- fp32 -> bf16 table ----------------
__global__ void k_conv(const float* __restrict__ Etab){
  int idx = blockIdx.x*256 + threadIdx.x;   // 8 floats each
  const float4* s = (const float4*)Etab;
  float4 a = s[idx*2], b = s[idx*2+1];
  float x[8] = {a.x,a.y,a.z,a.w,b.x,b.y,b.z,b.w};
  uint4 u;
  unsigned short hs[8];
  #pragma unroll
  for (int i = 0; i < 8; i++) hs[i] = __bfloat16_as_ushort(__float2bfloat16(x[i]));
  u.x = (uint32_t)hs[0] | ((uint32_t)hs[1]<<16);
  u.y = (uint32_t)hs[2] | ((uint32_t)hs[3]<<16);
  u.z = (uint32_t)hs[4] | ((uint32_t)hs[5]<<16);
  u.w = (uint32_t)hs[6] | ((uint32_t)hs[7]<<16);
  ((uint4*)g_Ebf)[idx] = u;
}

// ---------------- per-entity precompute: zz, g, c ----------------
__global__ void k_pre_e(const float* __restrict__ Etab,
                        const float* __restrict__ rules,
                        const int* __restrict__ qrelp){
  __shared__ __align__(16) float rs[R_*D_];
  int tid = threadIdx.x;
  for (int i = tid; i < R_*D_; i += blockDim.x) rs[i] = rules[i];
  __syncthreads();
  int qrel = *qrelp;
  int lane = tid & 31, warp = tid >> 5;
  int e = blockIdx.x*8 + warp;
  float4 zv = ((const float4*)(Etab + (size_t)e*D_))[lane];
  float zz = wsum(dot4(zv, zv));
  float4 qv = ((const float4*)(rs + qrel*D_))[lane];
  float zq = wsum(dot4(zv, qv));
  if (lane == 0) g_g[e] = zz + 2.f*zq;
  #pragma unroll
  for (int r = 0; r < R_; r++){
    float4 rv = ((const float4*)(rs + r*D_))[lane];
    float rz = wsum(dot4(zv, rv));
    if (lane == 0) g_c[r*E_ + e] = zz - 2.f*rz;
  }
}

// ---------------- per-batch precompute: u, v ----------------
__global__ void k_pre_b(const float* __restrict__ Etab,
                        const float* __restrict__ rules,
                        const int* __restrict__ head,
                        const int* __restrict__ tail,
                        const int* __restrict__ qrelp){
  __shared__ __align__(16) float rs[R_*D_];
  __shared__ float rr[R_];
  int tid = threadIdx.x;
  for (int i = tid; i < R_*D_; i += blockDim.x) rs[i] = rules[i];
  __syncthreads();
  if (tid < R_){
    float s = 0.f;
    for (int k = 0; k < D_; k++) s = fmaf(rs[tid*D_+k], rs[tid*D_+k], s);
    rr[tid] = s;
  }
  __syncthreads();
  int qrel = *qrelp;
  int lane = tid & 31, warp = tid >> 5;
  int b = blockIdx.x*8 + warp;
  float4 hv = ((const float4*)(Etab + (size_t)head[b]*D_))[lane];
  float4 tv = ((const float4*)(Etab + (size_t)tail[b]*D_))[lane];
  float hh = wsum(dot4(hv, hv));
  float tt = wsum(dot4(tv, tv));
  float4 qv = ((const float4*)(rs + qrel*D_))[lane];
  float tq = wsum(dot4(tv, qv));
  if (lane == 0) g_v[b] = tt + rr[qrel] - 2.f*tq;
  #pragma unroll
  for (int r = 0; r < R_; r++){
    float4 rv = ((const float4*)(rs + r*D_))[lane];
    float hr = wsum(dot4(hv, rv));
    if (lane == 0) g_u[b*R_ + r] = hh + rr[r] + 2.f*hr;
  }
}

// ---------------- main mma.sync fused kernel ----------------
// SMEM layout (bytes):
// [0, 67584): union { A tile [128][256B] @0, B tile @32768 } | stage [128][132] f32
// [67584, +4096): us [64][16]
// [71680, +8192): cs [16][128]
// [79872, +512):  gs [128]
// [80384, +256):  vs [64]
// [80640, +256):  hix  [80896, +256): tix
#define OFF_B 32768
#define OFF_US 67584
#define OFF_CS 71680
#define OFF_GS 79872
#define OFF_VS 80384
#define OFF_HIX 80640
#define OFF_TIX 80896
#define SMEM_BYTES 81152
#define SP 132   // stage pitch (floats)

__global__ __launch_bounds__(256,2) void k_main(const int* __restrict__ head,
                                                const int* __restrict__ tail){
  extern __shared__ __align__(16) char smc[];
  uint32_t sb = smem_u32(smc);
  float* stage = (float*)smc;
  float* us = (float*)(smc + OFF_US);
  float* cs = (float*)(smc + OFF_CS);
  float* gs = (float*)(smc + OFF_GS);
  float* vs = (float*)(smc + OFF_VS);
  int* hix = (int*)(smc + OFF_HIX);
  int* tix = (int*)(smc + OFF_TIX);

  int tid = threadIdx.x, wid = tid >> 5, lane = tid & 31;
  int e0 = blockIdx.x * ET2, b0 = blockIdx.y * BT;

  if (tid < 64){ hix[tid] = head[b0+tid]; tix[tid] = tail[b0+tid]; vs[tid] = g_v[b0+tid]; }
  if (tid >= 128) gs[tid-128] = g_g[e0 + tid - 128];
  for (int i = tid; i < BT*R_; i += 256) us[i] = g_u[b0*R_ + i];
  for (int i = tid; i < R_*ET2; i += 256){
    int r = i >> 7, e = i & 127;
    cs[i] = g_c[r*E_ + e0 + e];
  }

  // ---- load bf16 tiles into swizzled SMEM (16B chunk ^= row&7) ----
  const uint4* T = (const uint4*)g_Ebf;   // 16 uint4 per entity row
  #pragma unroll
  for (int it = 0; it < 16; it++){
    int idx = it*256 + tid;
    int ch = idx & 15, row = (idx >> 4) & 127, sel = idx >> 11;  // 0:A 1:B
    int ent = sel ? (e0 + row) : ((row < 64) ? hix[row] : tix[row-64]);
    uint4 v = T[ent*16 + ch];
    *(uint4*)(smc + sel*OFF_B + row*256 + (((uint32_t)ch ^ (row & 7)) << 4)) = v;
  }
  __syncthreads();

  // ---- mma.sync: D[128 rows][128 cols]; warp (wm, wn) owns 64x32 ----
  int wm = wid >> 2, wn = wid & 3;
  int lrow = lane & 15, lhi = lane >> 4;

  uint32_t a_base[4], b_base[2];
  uint32_t a_sw[4], b_sw[2];
  #pragma unroll
  for (int mi = 0; mi < 4; mi++){
    int r = wm*64 + mi*16 + lrow;
    a_base[mi] = sb + r*256; a_sw[mi] = (uint32_t)(r & 7);
  }
  #pragma unroll
  for (int nj = 0; nj < 2; nj++){
    int r = wn*32 + nj*16 + lrow;
    b_base[nj] = sb + OFF_B + r*256; b_sw[nj] = (uint32_t)(r & 7);
  }

  float acc[4][4][4];
  #pragma unroll
  for (int mi = 0; mi < 4; mi++)
    #pragma unroll
    for (int ni = 0; ni < 4; ni++)
      #pragma unroll
      for (int q = 0; q < 4; q++) acc[mi][ni][q] = 0.f;

  #pragma unroll
  for (int kk = 0; kk < 8; kk++){
    uint32_t c = (uint32_t)(kk*2 + lhi);
    uint32_t ra[4][4], rb[2][4];
    #pragma unroll
    for (int mi = 0; mi < 4; mi++)
      ldm4(ra[mi][0], ra[mi][1], ra[mi][2], ra[mi][3],
           a_base[mi] + ((c ^ a_sw[mi]) << 4));
    #pragma unroll
    for (int nj = 0; nj < 2; nj++)
      ldm4(rb[nj][0], rb[nj][1], rb[nj][2], rb[nj][3],
           b_base[nj] + ((c ^ b_sw[nj]) << 4));
    #pragma unroll
    for (int mi = 0; mi < 4; mi++)
      #pragma unroll
      for (int ni = 0; ni < 4; ni++){
        int nj = ni >> 1, sub = ni & 1;
        mma16816(acc[mi][ni], ra[mi], rb[nj][sub], rb[nj][2+sub]);
      }
  }

  __syncthreads();   // everyone done reading tiles before stage overwrite

  // ---- write D to stage [128][SP] (rows 0-63 hz, 64-127 zt) ----
  {
    int rb0 = wm*64 + (lane >> 2);
    int cb0 = wn*32 + (lane & 3)*2;
    #pragma unroll
    for (int mi = 0; mi < 4; mi++)
      #pragma unroll
      for (int ni = 0; ni < 4; ni++){
        *(float2*)(stage + (rb0 + mi*16)*SP + cb0 + ni*8)
          = make_float2(acc[mi][ni][0], acc[mi][ni][1]);
        *(float2*)(stage + (rb0 + mi*16 + 8)*SP + cb0 + ni*8)
          = make_float2(acc[mi][ni][2], acc[mi][ni][3]);
      }
  }
  __syncthreads();

  // ---- epilogue: warp w -> b rows w*8..w*8+7; lane -> 4 e's ----
  float4 gg = *(const float4*)(gs + lane*4);
  int bl0 = wid*8;
  #pragma unroll
  for (int b = 0; b < 8; b++){
    int bl = bl0 + b;
    float vb = vs[bl];
    float4 hz4 = *(const float4*)(stage + bl*SP + lane*4);
    float4 zt4 = *(const float4*)(stage + (64+bl)*SP + lane*4);
    float s2x = sqrt_approx(fmaxf(fmaf(-2.f, zt4.x, vb + gg.x), 0.f));
    float s2y = sqrt_approx(fmaxf(fmaf(-2.f, zt4.y, vb + gg.y), 0.f));
    float s2z = sqrt_approx(fmaxf(fmaf(-2.f, zt4.z, vb + gg.z), 0.f));
    float s2w = sqrt_approx(fmaxf(fmaf(-2.f, zt4.w, vb + gg.w), 0.f));
    float S1x = 0.f, S1y = 0.f, S1z = 0.f, S1w = 0.f;
    #pragma unroll
    for (int r = 0; r < R_; r++){
      float ur = us[bl*R_ + r];
      float4 cr = *(const float4*)(cs + r*128 + lane*4);
      S1x += sqrt_approx(fmaxf(fmaf(-2.f, hz4.x, ur + cr.x), 0.f));
      S1y += sqrt_approx(fmaxf(fmaf(-2.f, hz4.y, ur + cr.y), 0.f));
      S1z += sqrt_approx(fmaxf(fmaf(-2.f, hz4.z, ur + cr.z), 0.f));
      S1w += sqrt_approx(fmaxf(fmaf(-2.f, hz4.w, ur + cr.w), 0.f));
    }
    float a = fmaf(S1x, s2x, fmaf(S1y, s2y, fmaf(S1z, s2z, S1w*s2w)));
    a = wsum(a);
    if (lane == 0) g_part[(size_t)(b0 + bl)*NTILE_E + blockIdx.x] = a;
  }
}

// ---------------- final deterministic reduction ----------------
__global__ void k_final(float* __restrict__ out){
  int warp = threadIdx.x >> 5, lane = threadIdx.x & 31;
  int b = blockIdx.x*8 + warp;
  const float* p = g_part + (size_t)b*NTILE_E;
  float s = p[lane] + p[lane+32];
  s = wsum(s);
  if (lane == 0) out[b] = s * (1.f/(float)E_);
}

extern "C" void kernel_launch(void* const* d_in, const int* in_sizes, int n_in,
                              void* d_out, int out_size){
  const int*   head  = (const int*)d_in[0];
  const int*   tail  = (const int*)d_in[1];
  const int*   qrel  = (const int*)d_in[2];
  // d_in[3] = depth (fixed at 1, unused)
  const float* Etab  = (const float*)d_in[4];
  const float* rules = (const float*)d_in[5];
  float* out = (float*)d_out;

  cudaFuncSetAttribute(k_main, cudaFuncAttributeMaxDynamicSharedMemorySize, SMEM_BYTES);

  k_conv<<<E_*D_/(256*8), 256>>>(Etab);
  k_pre_e<<<E_/8, 256>>>(Etab, rules, qrel);
  k_pre_b<<<B_/8, 256>>>(Etab, rules, head, tail, qrel);
  dim3 grid(NTILE_E, B_/BT);
  k_main<<<grid, 256, SMEM_BYTES>>>(head, tail);
  k_final<<<B_/8, 256>>>(out);
}